// round 16
// baseline (speedup 1.0000x reference)
#include <cuda_runtime.h>
#include <cuda_fp16.h>
#include <cstdint>

// Problem constants
#define BATCH 8
#define SEQ   4096
#define DIM   512
#define HEADS 8
#define DH    64
#define INNER 512          // HEADS*DH
#define QKV_COLS 1536      // 3*INNER
#define ROWS  (BATCH*SEQ)  // 32768
#define EPS   1e-5f

// ---------------------------------------------------------------------------
// Scratch (device globals; no allocation allowed) — fp16 everywhere
// ---------------------------------------------------------------------------
__device__ __half g_qkvh[(size_t)ROWS * QKV_COLS];          // 100 MB fp16 q|k|v
__device__ __half g_xh[(size_t)ROWS * DIM];                 // 32 MB
__device__ __half g_wh[(size_t)QKV_COLS * DIM];             // 1.5 MB
__device__ __half g_qh[(size_t)ROWS * INNER];               // post LN/RoPE
__device__ __half g_kh[(size_t)ROWS * INNER];
__device__ __half g_vh[(size_t)ROWS * INNER];
__device__ __half g_mh[(size_t)BATCH * DIM * INNER];        // 4 MB
__device__ float  g_dots[BATCH * HEADS * DH * DH];          // 1 MB (262144 floats)

// ---------------------------------------------------------------------------
// PTX primitives (arch-agnostic; safe under .target sm_103)
// ---------------------------------------------------------------------------
__device__ __forceinline__ void cp16(uint32_t sdst, const void* gsrc) {
    asm volatile("cp.async.cg.shared.global [%0], [%1], 16;"
                 :: "r"(sdst), "l"(gsrc) : "memory");
}
__device__ __forceinline__ void cp_commit() {
    asm volatile("cp.async.commit_group;" ::: "memory");
}
template <int N> __device__ __forceinline__ void cp_wait() {
    asm volatile("cp.async.wait_group %0;" :: "n"(N) : "memory");
}
__device__ __forceinline__ void ldsm4(uint32_t* r, uint32_t a) {
    asm volatile("ldmatrix.sync.aligned.m8n8.x4.shared.b16 {%0,%1,%2,%3}, [%4];"
                 : "=r"(r[0]), "=r"(r[1]), "=r"(r[2]), "=r"(r[3]) : "r"(a));
}
__device__ __forceinline__ void ldsm4t(uint32_t* r, uint32_t a) {
    asm volatile("ldmatrix.sync.aligned.m8n8.x4.trans.shared.b16 {%0,%1,%2,%3}, [%4];"
                 : "=r"(r[0]), "=r"(r[1]), "=r"(r[2]), "=r"(r[3]) : "r"(a));
}
__device__ __forceinline__ void mma16816h(float* c, const uint32_t* a, const uint32_t* b) {
    asm volatile(
        "mma.sync.aligned.m16n8k16.row.col.f32.f16.f16.f32 "
        "{%0,%1,%2,%3}, {%4,%5,%6,%7}, {%8,%9}, {%0,%1,%2,%3};"
        : "+f"(c[0]), "+f"(c[1]), "+f"(c[2]), "+f"(c[3])
        : "r"(a[0]), "r"(a[1]), "r"(a[2]), "r"(a[3]), "r"(b[0]), "r"(b[1]));
}
__device__ __forceinline__ float warp_sum(float v) {
#pragma unroll
    for (int o = 16; o > 0; o >>= 1) v += __shfl_xor_sync(0xffffffffu, v, o);
    return v;
}

// ---------------------------------------------------------------------------
// GEMM: 128x128 tile, BK=64 (8 iters, half the barriers), 3-stage ring with
// wait<1> slack, XOR-swizzled 128B rows: chunk' = chunk ^ (row&7).
// 2 CTAs/SM (3 x 32KB = 96KB/CTA), 1 sync/iter. fp16 single-pass.
// ---------------------------------------------------------------------------
#define BK 64
#define ROWB 128                       // bytes per row (64 fp16, no pad)
#define MAT_BYTES (128 * ROWB)         // 16384
#define STAGE_BYTES (2 * MAT_BYTES)    // A|B = 32768
#define GEMM_SMEM (3 * STAGE_BYTES)    // 98304

__device__ __forceinline__ void stage_load(uint32_t sbase,
                                           const __half* __restrict__ A,
                                           const __half* __restrict__ B,
                                           int k0, int tid) {
#pragma unroll
    for (int hh = 0; hh < 4; hh++) {
        int i = tid + hh * 256;        // 0..1023
        int row = i >> 3, c8 = i & 7;
        int csw = c8 ^ (row & 7);
        uint32_t so = sbase + (uint32_t)(row * ROWB + csw * 16);
        size_t go = (size_t)row * 512 + k0 + c8 * 8;
        cp16(so,             A + go);
        cp16(so + MAT_BYTES, B + go);
    }
}

// Fills acc[4][4][4]; warp tile 64x32 (wm=wid>>2, wn=wid&3).
__device__ __forceinline__ void tc_mainloop(const __half* __restrict__ A,
                                            const __half* __restrict__ B,
                                            float acc[4][4][4]) {
    extern __shared__ char sm[];
    const uint32_t sbase = (uint32_t)__cvta_generic_to_shared(sm);
    const int tid = threadIdx.x;
    const int lane = tid & 31;
    const int wid = tid >> 5;
    const int wm = wid >> 2;
    const int wn = wid & 3;
    const int la = lane & 15;

    // A: row = wm*64 + la (+ mi*16, mi*16 ≡ 0 mod 8); chunk = kk*2 + (lane>>4)
    const int a_row = wm * 64 + la;
    const int a_sel = la & 7;
    const int a_ch  = lane >> 4;               // 0/1
    // B merged ldsm4: row = wn*32 + b_rowl (+ nip*16); chunk = kk*2 + ((lane>>3)&1)
    const int b_rowl = ((lane >> 4) * 8) + (lane & 7);
    const int b_row = wn * 32 + b_rowl;
    const int b_sel = b_rowl & 7;
    const int b_ch  = (lane >> 3) & 1;         // 0/1

#pragma unroll
    for (int mi = 0; mi < 4; mi++)
#pragma unroll
        for (int ni = 0; ni < 4; ni++)
#pragma unroll
            for (int j = 0; j < 4; j++) acc[mi][ni][j] = 0.0f;

    stage_load(sbase, A, B, 0, tid);
    cp_commit();
    stage_load(sbase + STAGE_BYTES, A, B, BK, tid);
    cp_commit();

    for (int c = 0; c < 8; c++) {
        if (c < 7) cp_wait<1>(); else cp_wait<0>();
        __syncthreads();
        if (c + 2 < 8) {
            stage_load(sbase + (uint32_t)(((c + 2) % 3) * STAGE_BYTES),
                       A, B, (c + 2) * BK, tid);
            cp_commit();
        }

        const uint32_t sb = sbase + (uint32_t)((c % 3) * STAGE_BYTES);
#pragma unroll
        for (int kk = 0; kk < 4; kk++) {
            const uint32_t aco = (uint32_t)((((kk * 2) + a_ch) ^ a_sel) * 16);
            const uint32_t bco = (uint32_t)((((kk * 2) + b_ch) ^ b_sel) * 16);

            uint32_t bh[2][4];
#pragma unroll
            for (int nip = 0; nip < 2; nip++) {
                uint32_t bd = sb + MAT_BYTES +
                              (uint32_t)((b_row + nip * 16) * ROWB) + bco;
                ldsm4(bh[nip], bd);
            }
            uint32_t ah[2][4];
            {
                uint32_t ad0 = sb + (uint32_t)(a_row * ROWB) + aco;
                ldsm4(ah[0], ad0);
            }
#pragma unroll
            for (int mi = 0; mi < 4; mi++) {
                const int cur = mi & 1, nxt = cur ^ 1;
                if (mi < 3) {
                    uint32_t adn = sb + (uint32_t)((a_row + (mi + 1) * 16) * ROWB) + aco;
                    ldsm4(ah[nxt], adn);
                }
#pragma unroll
                for (int ni = 0; ni < 4; ni++)
                    mma16816h(acc[mi][ni], ah[cur], &bh[ni >> 1][(ni & 1) * 2]);
            }
        }
    }
}

// ---------------------------------------------------------------------------
// QKV GEMM -> fp16 g_qkvh (half2 stores)
// ---------------------------------------------------------------------------
__global__ __launch_bounds__(256, 2) void gemm_qkv_tc(void) {
    const size_t bm = (size_t)blockIdx.y * 128, bn = (size_t)blockIdx.x * 128;

    float acc[4][4][4];
    tc_mainloop(g_xh + bm * 512, g_wh + bn * 512, acc);

    const int tid = threadIdx.x;
    const int lane = tid & 31;
    const int wid = tid >> 5;
    const int wm = wid >> 2, wn = wid & 3;
    const int r0 = lane >> 2, c0 = (lane & 3) * 2;
    __half* C = g_qkvh + bm * QKV_COLS + bn;

#pragma unroll
    for (int mi = 0; mi < 4; mi++)
#pragma unroll
        for (int ni = 0; ni < 4; ni++) {
            int row = wm * 64 + mi * 16 + r0;
            int col = wn * 32 + ni * 8 + c0;
            *(__half2*)(C + (size_t)row * QKV_COLS + col) =
                __floats2half2_rn(acc[mi][ni][0], acc[mi][ni][1]);
            *(__half2*)(C + (size_t)(row + 8) * QKV_COLS + col) =
                __floats2half2_rn(acc[mi][ni][2], acc[mi][ni][3]);
        }
}

// ---------------------------------------------------------------------------
// Output GEMM: out[b] = q[b] @ McatT[b]^T + bias
// ---------------------------------------------------------------------------
__global__ __launch_bounds__(256, 2) void gemm_out_tc(const float* __restrict__ bout,
                                                      float* __restrict__ out) {
    const int b = blockIdx.z;
    const size_t arow = (size_t)b * SEQ + (size_t)blockIdx.y * 128;
    const size_t brow = (size_t)b * DIM + (size_t)blockIdx.x * 128;

    float acc[4][4][4];
    tc_mainloop(g_qh + arow * 512, g_mh + brow * 512, acc);

    const int tid = threadIdx.x;
    const int lane = tid & 31;
    const int wid = tid >> 5;
    const int wm = wid >> 2, wn = wid & 3;
    const int r0 = lane >> 2, c0 = (lane & 3) * 2;
    float* C = out + arow * DIM + blockIdx.x * 128;
    const float* bias = bout + blockIdx.x * 128;

#pragma unroll
    for (int mi = 0; mi < 4; mi++)
#pragma unroll
        for (int ni = 0; ni < 4; ni++) {
            int row = wm * 64 + mi * 16 + r0;
            int col = wn * 32 + ni * 8 + c0;
            float b0 = bias[col], b1 = bias[col + 1];
            *(float2*)(C + (size_t)row * DIM + col) =
                make_float2(acc[mi][ni][0] + b0, acc[mi][ni][1] + b1);
            *(float2*)(C + (size_t)(row + 8) * DIM + col) =
                make_float2(acc[mi][ni][2] + b0, acc[mi][ni][3] + b1);
        }
}

// ---------------------------------------------------------------------------
// fp16 convert; blocks past n4 zero g_dots (fused zero_dots).
// ---------------------------------------------------------------------------
#define DOTS_F4 (BATCH * HEADS * DH * DH / 4)   // 65536 float4

__global__ __launch_bounds__(256) void split_kernel(const float* __restrict__ src,
                                                    __half* __restrict__ dst,
                                                    int n4, int zero_dots) {
    int i = blockIdx.x * 256 + threadIdx.x;
    if (i < n4) {
        float4 v = ((const float4*)src)[i];
        ((__half2*)dst)[i * 2 + 0] = __floats2half2_rn(v.x, v.y);
        ((__half2*)dst)[i * 2 + 1] = __floats2half2_rn(v.z, v.w);
    } else if (zero_dots) {
        int z = i - n4;
        if (z < DOTS_F4)
            ((float4*)g_dots)[z] = make_float4(0.f, 0.f, 0.f, 0.f);
    }
}

// ---------------------------------------------------------------------------
// LN(k,v) + RoPE(q,k) reading fp16 g_qkvh, writing fp16 q/k/v.
// One warp per (b,n,h) row; lane holds elems (2*lane, 2*lane+1).
// ---------------------------------------------------------------------------
__global__ __launch_bounds__(256) void ln_rope_split_kernel(
        const float* __restrict__ pos,
        const float* __restrict__ gk, const float* __restrict__ bk,
        const float* __restrict__ gv, const float* __restrict__ bv) {
    const int warp = threadIdx.x >> 5;
    const int lane = threadIdx.x & 31;
    const int r = blockIdx.x * 8 + warp;     // 0 .. B*N*H-1
    const int b = r >> 15;
    const int rem = r & 32767;
    const int n = rem >> 3;
    const int h = rem & 7;
    const int token = b * SEQ + n;

    const __half* qp = g_qkvh + (size_t)token * QKV_COLS + h * DH;
    const __half* kp = qp + INNER;
    const __half* vp = qp + 2 * INNER;

    __half2 qh2 = *(const __half2*)(qp + 2 * lane);
    __half2 kh2 = *(const __half2*)(kp + 2 * lane);
    __half2 vh2 = *(const __half2*)(vp + 2 * lane);
    float qe0 = __low2float(qh2), qe1 = __high2float(qh2);
    float ke0 = __low2float(kh2), ke1 = __high2float(kh2);
    float ve0 = __low2float(vh2), ve1 = __high2float(vh2);
    const int e0 = 2 * lane, e1 = 2 * lane + 1;

    // LayerNorm k
    float mu = warp_sum(ke0 + ke1) * (1.0f / 64.0f);
    float d0 = ke0 - mu, d1 = ke1 - mu;
    float var = warp_sum(d0 * d0 + d1 * d1) * (1.0f / 64.0f);
    float inv = rsqrtf(var + EPS);
    ke0 = d0 * inv * gk[e0] + bk[e0];
    ke1 = d1 * inv * gk[e1] + bk[e1];

    // LayerNorm v
    mu = warp_sum(ve0 + ve1) * (1.0f / 64.0f);
    d0 = ve0 - mu; d1 = ve1 - mu;
    var = warp_sum(d0 * d0 + d1 * d1) * (1.0f / 64.0f);
    inv = rsqrtf(var + EPS);
    ve0 = d0 * inv * gv[e0] + bv[e0];
    ve1 = d1 * inv * gv[e1] + bv[e1];

    // 2D RoPE: partner of elem e is e^16 -> lane^8, same slot.
    const float cxp = pos[(size_t)token * 2 + 0];
    const float cyp = pos[(size_t)token * 2 + 1];
    float qp0 = __shfl_xor_sync(0xffffffffu, qe0, 8);
    float qp1 = __shfl_xor_sync(0xffffffffu, qe1, 8);
    float kp0 = __shfl_xor_sync(0xffffffffu, ke0, 8);
    float kp1 = __shfl_xor_sync(0xffffffffu, ke1, 8);

#pragma unroll
    for (int s = 0; s < 2; s++) {
        const int e = s ? e1 : e0;
        const int j = e & 31;
        const float coord = (e < 32) ? cxp : cyp;
        float invf = exp2f(-0.830482023721841f * (float)(j & 15)) * 64.0f;
        float sv, cv;
        sincosf(coord * invf, &sv, &cv);
        const float sgn = (j < 16) ? -1.0f : 1.0f;
        if (s == 0) {
            qe0 = qe0 * cv + sgn * qp0 * sv;
            ke0 = ke0 * cv + sgn * kp0 * sv;
        } else {
            qe1 = qe1 * cv + sgn * qp1 * sv;
            ke1 = ke1 * cv + sgn * kp1 * sv;
        }
    }

    const size_t base = (size_t)token * 512 + h * DH;
    *(__half2*)(g_qh + base + 2 * lane) = __floats2half2_rn(qe0, qe1);
    *(__half2*)(g_kh + base + 2 * lane) = __floats2half2_rn(ke0, ke1);
    *(__half2*)(g_vh + base + 2 * lane) = __floats2half2_rn(ve0, ve1);
}

// ---------------------------------------------------------------------------
// dots = K^T V via HMMA fp16, K-major via ldmatrix.trans.
// grid (64 bh, 8 splits of 512 tokens). 128 threads = 4 warps (2x2 of 32x32).
// ---------------------------------------------------------------------------
#define KV_SR 72                       // fp16 elems per row = 144B (16B multiple)
#define KV_TILE (64 * KV_SR * 2)       // 9216
#define KV_STAGE (2 * KV_TILE)         // 18432 (K|V)
#define KV_SMEM (3 * KV_STAGE)         // 55296

__device__ __forceinline__ void kv_stage_load(uint32_t sb, int b, int h, int tok0,
                                              int tid) {
#pragma unroll
    for (int hh = 0; hh < 8; hh++) {
        int i = tid + hh * 128;        // 0..1023
        int op = i >> 9;               // 0: k, 1: v
        int ii = i & 511;
        int row = ii >> 3, ch = ii & 7;
        const __half* src = op ? g_vh : g_kh;
        cp16(sb + (uint32_t)(op * KV_TILE + row * (KV_SR * 2) + ch * 16),
             src + ((size_t)(b * SEQ + tok0 + row)) * 512 + h * 64 + ch * 8);
    }
}

__global__ __launch_bounds__(128) void kv_dots_kernel() {
    extern __shared__ char sm[];
    const uint32_t sbase = (uint32_t)__cvta_generic_to_shared(sm);
    const int bh = blockIdx.x;
    const int b = bh >> 3, h = bh & 7;
    const int tok0 = blockIdx.y * 512;
    const int tid = threadIdx.x;
    const int lane = tid & 31;
    const int wid = tid >> 5;
    const int wm = wid >> 1;
    const int wn = wid & 1;

    const int t_row = (lane & 7) + ((lane >> 4) & 1) * 8;
    const int a_col = ((lane >> 3) & 1) * 8;
    const int b_row = (lane & 7) + ((lane >> 3) & 1) * 8;
    const int b_col = (lane >> 4) * 8;

    float acc[2][4][4];
#pragma unroll
    for (int mf = 0; mf < 2; mf++)
#pragma unroll
        for (int nf = 0; nf < 4; nf++)
#pragma unroll
            for (int j = 0; j < 4; j++) acc[mf][nf][j] = 0.0f;

    kv_stage_load(sbase, b, h, tok0, tid);
    cp_commit();
    kv_stage_load(sbase + KV_STAGE, b, h, tok0 + 64, tid);
    cp_commit();

    for (int s = 0; s < 8; s++) {
        if (s < 7) cp_wait<1>(); else cp_wait<0>();
        __syncthreads();
        if (s + 2 < 8) {
            kv_stage_load(sbase + (uint32_t)(((s + 2) % 3) * KV_STAGE),
                          b, h, tok0 + (s + 2) * 64, tid);
            cp_commit();
        }
        const uint32_t sb = sbase + (uint32_t)((s % 3) * KV_STAGE);
#pragma unroll
        for (int kt = 0; kt < 4; kt++) {
            const int kt0 = kt * 16;
            uint32_t aH[2][4], bH[2][4];
#pragma unroll
            for (int mf = 0; mf < 2; mf++) {
                int d0 = wm * 32 + mf * 16;
                uint32_t ad = sb + (uint32_t)((kt0 + t_row) * (KV_SR * 2) +
                                              (d0 + a_col) * 2);
                ldsm4t(aH[mf], ad);
            }
#pragma unroll
            for (int g = 0; g < 2; g++) {
                int e0 = wn * 32 + g * 16;
                uint32_t bd = sb + KV_TILE +
                              (uint32_t)((kt0 + b_row) * (KV_SR * 2) +
                                         (e0 + b_col) * 2);
                ldsm4t(bH[g], bd);
            }
#pragma unroll
            for (int mf = 0; mf < 2; mf++)
#pragma unroll
                for (int nf = 0; nf < 4; nf++)
                    mma16816h(acc[mf][nf], aH[mf], &bH[nf >> 1][(nf & 1) * 2]);
        }
    }

    float* dbase = g_dots + (size_t)bh * DH * DH;
    const int r0 = lane >> 2, c0 = (lane & 3) * 2;
#pragma unroll
    for (int mf = 0; mf < 2; mf++)
#pragma unroll
        for (int nf = 0; nf < 4; nf++) {
            int d = wm * 32 + mf * 16 + r0;
            int e = wn * 32 + nf * 8 + c0;
            atomicAdd(&dbase[d * DH + e],       acc[mf][nf][0]);
            atomicAdd(&dbase[d * DH + e + 1],   acc[mf][nf][1]);
            atomicAdd(&dbase[(d + 8) * DH + e],     acc[mf][nf][2]);
            atomicAdd(&dbase[(d + 8) * DH + e + 1], acc[mf][nf][3]);
        }
}

// ---------------------------------------------------------------------------
// McatT[b][o, h*64+d] = (1/SEQ) * sum_e dots[b,h,d,e] * Wout[o, h*64+e] (fp16)
// ---------------------------------------------------------------------------
__global__ __launch_bounds__(256) void mcat_kernel(const float* __restrict__ Wout) {
    __shared__ float ds[64][65];
    __shared__ float ws[64][65];

    const int bh = blockIdx.x;
    const int b = bh >> 3, h = bh & 7;
    const int o0 = blockIdx.y * 64;
    const int tid = threadIdx.x;

    for (int i = tid; i < 4096; i += 256) {
        int d = i >> 6, e = i & 63;
        ds[d][e] = g_dots[(size_t)bh * 4096 + i];
        ws[d][e] = Wout[(size_t)(o0 + d) * INNER + h * DH + e];
    }
    __syncthreads();

    for (int t = tid; t < 4096; t += 256) {
        int oL = t >> 6, d = t & 63;
        float acc = 0.0f;
#pragma unroll
        for (int e = 0; e < 64; e++) acc += ds[d][e] * ws[oL][e];
        acc *= (1.0f / (float)SEQ);
        size_t idx = ((size_t)b * DIM + (o0 + oL)) * 512 + h * DH + d;
        g_mh[idx] = __float2half(acc);
    }
}

// ---------------------------------------------------------------------------
// launch (single stream, fat launches)
// ---------------------------------------------------------------------------
extern "C" void kernel_launch(void* const* d_in, const int* in_sizes, int n_in,
                              void* d_out, int out_size) {
    const float* x    = (const float*)d_in[0];
    const float* pos  = (const float*)d_in[1];
    const float* Wqkv = (const float*)d_in[2];
    const float* gk   = (const float*)d_in[3];
    const float* bk   = (const float*)d_in[4];
    const float* gv   = (const float*)d_in[5];
    const float* bv   = (const float*)d_in[6];
    const float* Wout = (const float*)d_in[7];
    const float* bout = (const float*)d_in[8];
    float* out = (float*)d_out;

    static bool attr_done = false;
    if (!attr_done) {
        cudaFuncSetAttribute(gemm_qkv_tc,  cudaFuncAttributeMaxDynamicSharedMemorySize, GEMM_SMEM);
        cudaFuncSetAttribute(gemm_out_tc,  cudaFuncAttributeMaxDynamicSharedMemorySize, GEMM_SMEM);
        cudaFuncSetAttribute(kv_dots_kernel, cudaFuncAttributeMaxDynamicSharedMemorySize, KV_SMEM);
        attr_done = true;
    }

    void* p_xh; void* p_wh;
    cudaGetSymbolAddress(&p_xh, g_xh); cudaGetSymbolAddress(&p_wh, g_wh);

    // 1) fp16 converts; x-convert's tail blocks also zero g_dots
    int n4x = (ROWS * DIM) / 4;
    split_kernel<<<(n4x + DOTS_F4 + 255) / 256, 256>>>(x, (__half*)p_xh, n4x, 1);
    int n4w = (QKV_COLS * DIM) / 4;
    split_kernel<<<(n4w + 255) / 256, 256>>>(Wqkv, (__half*)p_wh, n4w, 0);

    // 2) qkv = x @ Wqkv^T (fp16 HMMA, BK=64) -> fp16 g_qkvh
    gemm_qkv_tc<<<dim3(QKV_COLS / 128, ROWS / 128), 256, GEMM_SMEM>>>();

    // 3) LN(k,v) + RoPE(q,k) -> fp16 q/k/v
    ln_rope_split_kernel<<<(BATCH * SEQ * HEADS) / 8, 256>>>(pos, gk, bk, gv, bv);

    // 4) dots = K^T V (fp16 HMMA, atomic over 8 splits)
    kv_dots_kernel<<<dim3(BATCH * HEADS, 8), 128, KV_SMEM>>>();

    // 5) McatT[b] = (dots[b] @ Wout^T)/SEQ (fp16)
    mcat_kernel<<<dim3(BATCH * HEADS, DIM / 64), 256>>>(Wout);

    // 6) out[b] = q[b] @ McatT[b]^T + b_out
    gemm_out_tc<<<dim3(DIM / 128, SEQ / 128, BATCH), 256, GEMM_SMEM>>>(bout, out);
}

// round 17
// speedup vs baseline: 1.0538x; 1.0538x over previous
#include <cuda_runtime.h>
#include <cuda_fp16.h>
#include <cstdint>

// Problem constants
#define BATCH 8
#define SEQ   4096
#define DIM   512
#define HEADS 8
#define DH    64
#define INNER 512          // HEADS*DH
#define QKV_COLS 1536      // 3*INNER
#define ROWS  (BATCH*SEQ)  // 32768
#define EPS   1e-5f

// ---------------------------------------------------------------------------
// Scratch (device globals; no allocation allowed) — fp16 everywhere
// ---------------------------------------------------------------------------
__device__ __half g_qkvh[(size_t)ROWS * QKV_COLS];          // 100 MB fp16 q|k|v
__device__ __half g_xh[(size_t)ROWS * DIM];                 // 32 MB
__device__ __half g_wh[(size_t)QKV_COLS * DIM];             // 1.5 MB
__device__ __half g_qh[(size_t)ROWS * INNER];               // post LN/RoPE
__device__ __half g_kh[(size_t)ROWS * INNER];
__device__ __half g_vh[(size_t)ROWS * INNER];
__device__ __half g_mh[(size_t)BATCH * DIM * INNER];        // 4 MB
__device__ float  g_dots[BATCH * HEADS * DH * DH];          // 1 MB

// ---------------------------------------------------------------------------
// PTX primitives (arch-agnostic; safe under .target sm_103)
// ---------------------------------------------------------------------------
__device__ __forceinline__ void cp16(uint32_t sdst, const void* gsrc) {
    asm volatile("cp.async.cg.shared.global [%0], [%1], 16;"
                 :: "r"(sdst), "l"(gsrc) : "memory");
}
__device__ __forceinline__ void cp_commit() {
    asm volatile("cp.async.commit_group;" ::: "memory");
}
template <int N> __device__ __forceinline__ void cp_wait() {
    asm volatile("cp.async.wait_group %0;" :: "n"(N) : "memory");
}
__device__ __forceinline__ void ldsm4(uint32_t* r, uint32_t a) {
    asm volatile("ldmatrix.sync.aligned.m8n8.x4.shared.b16 {%0,%1,%2,%3}, [%4];"
                 : "=r"(r[0]), "=r"(r[1]), "=r"(r[2]), "=r"(r[3]) : "r"(a));
}
__device__ __forceinline__ void ldsm4t(uint32_t* r, uint32_t a) {
    asm volatile("ldmatrix.sync.aligned.m8n8.x4.trans.shared.b16 {%0,%1,%2,%3}, [%4];"
                 : "=r"(r[0]), "=r"(r[1]), "=r"(r[2]), "=r"(r[3]) : "r"(a));
}
__device__ __forceinline__ void mma16816h(float* c, const uint32_t* a, const uint32_t* b) {
    asm volatile(
        "mma.sync.aligned.m16n8k16.row.col.f32.f16.f16.f32 "
        "{%0,%1,%2,%3}, {%4,%5,%6,%7}, {%8,%9}, {%0,%1,%2,%3};"
        : "+f"(c[0]), "+f"(c[1]), "+f"(c[2]), "+f"(c[3])
        : "r"(a[0]), "r"(a[1]), "r"(a[2]), "r"(a[3]), "r"(b[0]), "r"(b[1]));
}
__device__ __forceinline__ float warp_sum(float v) {
#pragma unroll
    for (int o = 16; o > 0; o >>= 1) v += __shfl_xor_sync(0xffffffffu, v, o);
    return v;
}

// ---------------------------------------------------------------------------
// GEMM: 128x128 tile, BK=32, 3-stage cp.async ring (wait<1> slack),
// XOR-swizzled 64B rows, 2 CTAs/SM, 1 sync/iter. fp16 single-pass.
// ---------------------------------------------------------------------------
#define BK 32
#define ROWB 64                        // bytes per row (32 fp16, no pad)
#define MAT_BYTES (128 * ROWB)         // 8192
#define STAGE_BYTES (2 * MAT_BYTES)    // A|B = 16384
#define GEMM_SMEM (3 * STAGE_BYTES)    // 49152

__device__ __forceinline__ void stage_load(uint32_t sbase,
                                           const __half* __restrict__ A,
                                           const __half* __restrict__ B,
                                           int k0, int tid) {
#pragma unroll
    for (int hh = 0; hh < 2; hh++) {
        int i = tid + hh * 256;
        int row = i >> 2, c8 = i & 3;
        int csw = c8 ^ ((row >> 1) & 3);
        uint32_t so = sbase + (uint32_t)(row * ROWB + csw * 16);
        size_t go = (size_t)row * 512 + k0 + c8 * 8;
        cp16(so,             A + go);
        cp16(so + MAT_BYTES, B + go);
    }
}

// Fills acc[4][4][4]; warp tile 64x32 (wm=wid>>2, wn=wid&3).
__device__ __forceinline__ void tc_mainloop(const __half* __restrict__ A,
                                            const __half* __restrict__ B,
                                            float acc[4][4][4]) {
    extern __shared__ char sm[];
    const uint32_t sbase = (uint32_t)__cvta_generic_to_shared(sm);
    const int tid = threadIdx.x;
    const int lane = tid & 31;
    const int wid = tid >> 5;
    const int wm = wid >> 2;
    const int wn = wid & 3;
    const int la = lane & 15;

    const int a_row = wm * 64 + la;
    const int a_sel = (la >> 1) & 3;
    const int a_ch  = lane >> 4;               // 0/1
    const int b_rowl = ((lane >> 4) * 8) + (lane & 7);
    const int b_row = wn * 32 + b_rowl;
    const int b_sel = (b_rowl >> 1) & 3;
    const int b_ch  = (lane >> 3) & 1;         // 0/1

#pragma unroll
    for (int mi = 0; mi < 4; mi++)
#pragma unroll
        for (int ni = 0; ni < 4; ni++)
#pragma unroll
            for (int j = 0; j < 4; j++) acc[mi][ni][j] = 0.0f;

    stage_load(sbase, A, B, 0, tid);
    cp_commit();
    stage_load(sbase + STAGE_BYTES, A, B, BK, tid);
    cp_commit();

    for (int c = 0; c < 16; c++) {
        if (c < 15) cp_wait<1>(); else cp_wait<0>();
        __syncthreads();
        if (c + 2 < 16) {
            stage_load(sbase + (uint32_t)(((c + 2) % 3) * STAGE_BYTES),
                       A, B, (c + 2) * BK, tid);
            cp_commit();
        }

        const uint32_t sb = sbase + (uint32_t)((c % 3) * STAGE_BYTES);
#pragma unroll
        for (int kk = 0; kk < 2; kk++) {
            const uint32_t aco = (uint32_t)((((kk * 2) + a_ch) ^ a_sel) * 16);
            const uint32_t bco = (uint32_t)((((kk * 2) + b_ch) ^ b_sel) * 16);

            uint32_t bh[2][4];
#pragma unroll
            for (int nip = 0; nip < 2; nip++) {
                uint32_t bd = sb + MAT_BYTES +
                              (uint32_t)((b_row + nip * 16) * ROWB) + bco;
                ldsm4(bh[nip], bd);
            }
            uint32_t ah[2][4];
            {
                uint32_t ad0 = sb + (uint32_t)(a_row * ROWB) + aco;
                ldsm4(ah[0], ad0);
            }
#pragma unroll
            for (int mi = 0; mi < 4; mi++) {
                const int cur = mi & 1, nxt = cur ^ 1;
                if (mi < 3) {
                    uint32_t adn = sb + (uint32_t)((a_row + (mi + 1) * 16) * ROWB) + aco;
                    ldsm4(ah[nxt], adn);
                }
#pragma unroll
                for (int ni = 0; ni < 4; ni++)
                    mma16816h(acc[mi][ni], ah[cur], &bh[ni >> 1][(ni & 1) * 2]);
            }
        }
    }
}

// ---------------------------------------------------------------------------
// QKV GEMM -> fp16 g_qkvh (half2 stores)
// ---------------------------------------------------------------------------
__global__ __launch_bounds__(256, 2) void gemm_qkv_tc(void) {
    const size_t bm = (size_t)blockIdx.y * 128, bn = (size_t)blockIdx.x * 128;

    float acc[4][4][4];
    tc_mainloop(g_xh + bm * 512, g_wh + bn * 512, acc);

    const int tid = threadIdx.x;
    const int lane = tid & 31;
    const int wid = tid >> 5;
    const int wm = wid >> 2, wn = wid & 3;
    const int r0 = lane >> 2, c0 = (lane & 3) * 2;
    __half* C = g_qkvh + bm * QKV_COLS + bn;

#pragma unroll
    for (int mi = 0; mi < 4; mi++)
#pragma unroll
        for (int ni = 0; ni < 4; ni++) {
            int row = wm * 64 + mi * 16 + r0;
            int col = wn * 32 + ni * 8 + c0;
            *(__half2*)(C + (size_t)row * QKV_COLS + col) =
                __floats2half2_rn(acc[mi][ni][0], acc[mi][ni][1]);
            *(__half2*)(C + (size_t)(row + 8) * QKV_COLS + col) =
                __floats2half2_rn(acc[mi][ni][2], acc[mi][ni][3]);
        }
}

// ---------------------------------------------------------------------------
// Output GEMM: out[b] = q[b] @ McatT[b]^T + bias
// ---------------------------------------------------------------------------
__global__ __launch_bounds__(256, 2) void gemm_out_tc(const float* __restrict__ bout,
                                                      float* __restrict__ out) {
    const int b = blockIdx.z;
    const size_t arow = (size_t)b * SEQ + (size_t)blockIdx.y * 128;
    const size_t brow = (size_t)b * DIM + (size_t)blockIdx.x * 128;

    float acc[4][4][4];
    tc_mainloop(g_qh + arow * 512, g_mh + brow * 512, acc);

    const int tid = threadIdx.x;
    const int lane = tid & 31;
    const int wid = tid >> 5;
    const int wm = wid >> 2, wn = wid & 3;
    const int r0 = lane >> 2, c0 = (lane & 3) * 2;
    float* C = out + arow * DIM + blockIdx.x * 128;
    const float* bias = bout + blockIdx.x * 128;

#pragma unroll
    for (int mi = 0; mi < 4; mi++)
#pragma unroll
        for (int ni = 0; ni < 4; ni++) {
            int row = wm * 64 + mi * 16 + r0;
            int col = wn * 32 + ni * 8 + c0;
            float b0 = bias[col], b1 = bias[col + 1];
            *(float2*)(C + (size_t)row * DIM + col) =
                make_float2(acc[mi][ni][0] + b0, acc[mi][ni][1] + b1);
            *(float2*)(C + (size_t)(row + 8) * DIM + col) =
                make_float2(acc[mi][ni][2] + b0, acc[mi][ni][3] + b1);
        }
}

// ---------------------------------------------------------------------------
// fp16 convert (x and Wqkv)
// ---------------------------------------------------------------------------
__global__ __launch_bounds__(256) void split_kernel(const float* __restrict__ src,
                                                    __half* __restrict__ dst,
                                                    int n4) {
    int i = blockIdx.x * 256 + threadIdx.x;
    if (i >= n4) return;
    float4 v = ((const float4*)src)[i];
    ((__half2*)dst)[i * 2 + 0] = __floats2half2_rn(v.x, v.y);
    ((__half2*)dst)[i * 2 + 1] = __floats2half2_rn(v.z, v.w);
}

// ---------------------------------------------------------------------------
// LN(k,v) + RoPE(q,k) reading fp16 g_qkvh, writing fp16 q/k/v.
// One warp per (b,n,h) row; lane holds elems (2*lane, 2*lane+1).
// Fast-math __sincosf: |arg| <= 64, error ~1e-5 << 4e-4 budget headroom.
// ---------------------------------------------------------------------------
__global__ __launch_bounds__(256) void ln_rope_split_kernel(
        const float* __restrict__ pos,
        const float* __restrict__ gk, const float* __restrict__ bk,
        const float* __restrict__ gv, const float* __restrict__ bv) {
    const int warp = threadIdx.x >> 5;
    const int lane = threadIdx.x & 31;
    const int r = blockIdx.x * 8 + warp;     // 0 .. B*N*H-1
    const int b = r >> 15;
    const int rem = r & 32767;
    const int n = rem >> 3;
    const int h = rem & 7;
    const int token = b * SEQ + n;

    const __half* qp = g_qkvh + (size_t)token * QKV_COLS + h * DH;
    const __half* kp = qp + INNER;
    const __half* vp = qp + 2 * INNER;

    __half2 qh2 = *(const __half2*)(qp + 2 * lane);
    __half2 kh2 = *(const __half2*)(kp + 2 * lane);
    __half2 vh2 = *(const __half2*)(vp + 2 * lane);
    float qe0 = __low2float(qh2), qe1 = __high2float(qh2);
    float ke0 = __low2float(kh2), ke1 = __high2float(kh2);
    float ve0 = __low2float(vh2), ve1 = __high2float(vh2);
    const int e0 = 2 * lane, e1 = 2 * lane + 1;

    // LayerNorm k
    float mu = warp_sum(ke0 + ke1) * (1.0f / 64.0f);
    float d0 = ke0 - mu, d1 = ke1 - mu;
    float var = warp_sum(d0 * d0 + d1 * d1) * (1.0f / 64.0f);
    float inv = rsqrtf(var + EPS);
    ke0 = d0 * inv * gk[e0] + bk[e0];
    ke1 = d1 * inv * gk[e1] + bk[e1];

    // LayerNorm v
    mu = warp_sum(ve0 + ve1) * (1.0f / 64.0f);
    d0 = ve0 - mu; d1 = ve1 - mu;
    var = warp_sum(d0 * d0 + d1 * d1) * (1.0f / 64.0f);
    inv = rsqrtf(var + EPS);
    ve0 = d0 * inv * gv[e0] + bv[e0];
    ve1 = d1 * inv * gv[e1] + bv[e1];

    // 2D RoPE: partner of elem e is e^16 -> lane^8, same slot.
    const float cxp = pos[(size_t)token * 2 + 0];
    const float cyp = pos[(size_t)token * 2 + 1];
    float qp0 = __shfl_xor_sync(0xffffffffu, qe0, 8);
    float qp1 = __shfl_xor_sync(0xffffffffu, qe1, 8);
    float kp0 = __shfl_xor_sync(0xffffffffu, ke0, 8);
    float kp1 = __shfl_xor_sync(0xffffffffu, ke1, 8);

#pragma unroll
    for (int s = 0; s < 2; s++) {
        const int e = s ? e1 : e0;
        const int j = e & 31;
        const float coord = (e < 32) ? cxp : cyp;
        float invf = exp2f(-0.830482023721841f * (float)(j & 15)) * 64.0f;
        float sv, cv;
        __sincosf(coord * invf, &sv, &cv);
        const float sgn = (j < 16) ? -1.0f : 1.0f;
        if (s == 0) {
            qe0 = qe0 * cv + sgn * qp0 * sv;
            ke0 = ke0 * cv + sgn * kp0 * sv;
        } else {
            qe1 = qe1 * cv + sgn * qp1 * sv;
            ke1 = ke1 * cv + sgn * kp1 * sv;
        }
    }

    const size_t base = (size_t)token * 512 + h * DH;
    *(__half2*)(g_qh + base + 2 * lane) = __floats2half2_rn(qe0, qe1);
    *(__half2*)(g_kh + base + 2 * lane) = __floats2half2_rn(ke0, ke1);
    *(__half2*)(g_vh + base + 2 * lane) = __floats2half2_rn(ve0, ve1);
}

// ---------------------------------------------------------------------------
// dots = K^T V via HMMA fp16, K-major via ldmatrix.trans.
// grid (64 bh, 4 splits of 1024 tokens). 128 threads = 4 warps (2x2 of 32x32).
// ---------------------------------------------------------------------------
#define KV_SR 72                       // fp16 elems per row = 144B (16B multiple)
#define KV_TILE (64 * KV_SR * 2)       // 9216
#define KV_STAGE (2 * KV_TILE)         // 18432 (K|V)
#define KV_SMEM (3 * KV_STAGE)         // 55296

__device__ __forceinline__ void kv_stage_load(uint32_t sb, int b, int h, int tok0,
                                              int tid) {
#pragma unroll
    for (int hh = 0; hh < 8; hh++) {
        int i = tid + hh * 128;        // 0..1023
        int op = i >> 9;               // 0: k, 1: v
        int ii = i & 511;
        int row = ii >> 3, ch = ii & 7;
        const __half* src = op ? g_vh : g_kh;
        cp16(sb + (uint32_t)(op * KV_TILE + row * (KV_SR * 2) + ch * 16),
             src + ((size_t)(b * SEQ + tok0 + row)) * 512 + h * 64 + ch * 8);
    }
}

__global__ __launch_bounds__(128) void kv_dots_kernel() {
    extern __shared__ char sm[];
    const uint32_t sbase = (uint32_t)__cvta_generic_to_shared(sm);
    const int bh = blockIdx.x;
    const int b = bh >> 3, h = bh & 7;
    const int tok0 = blockIdx.y * 1024;
    const int tid = threadIdx.x;
    const int lane = tid & 31;
    const int wid = tid >> 5;
    const int wm = wid >> 1;
    const int wn = wid & 1;

    const int t_row = (lane & 7) + ((lane >> 4) & 1) * 8;
    const int a_col = ((lane >> 3) & 1) * 8;
    const int b_row = (lane & 7) + ((lane >> 3) & 1) * 8;
    const int b_col = (lane >> 4) * 8;

    float acc[2][4][4];
#pragma unroll
    for (int mf = 0; mf < 2; mf++)
#pragma unroll
        for (int nf = 0; nf < 4; nf++)
#pragma unroll
            for (int j = 0; j < 4; j++) acc[mf][nf][j] = 0.0f;

    kv_stage_load(sbase, b, h, tok0, tid);
    cp_commit();
    kv_stage_load(sbase + KV_STAGE, b, h, tok0 + 64, tid);
    cp_commit();

    for (int s = 0; s < 16; s++) {
        if (s < 15) cp_wait<1>(); else cp_wait<0>();
        __syncthreads();
        if (s + 2 < 16) {
            kv_stage_load(sbase + (uint32_t)(((s + 2) % 3) * KV_STAGE),
                          b, h, tok0 + (s + 2) * 64, tid);
            cp_commit();
        }
        const uint32_t sb = sbase + (uint32_t)((s % 3) * KV_STAGE);
#pragma unroll
        for (int kt = 0; kt < 4; kt++) {
            const int kt0 = kt * 16;
            uint32_t aH[2][4], bH[2][4];
#pragma unroll
            for (int mf = 0; mf < 2; mf++) {
                int d0 = wm * 32 + mf * 16;
                uint32_t ad = sb + (uint32_t)((kt0 + t_row) * (KV_SR * 2) +
                                              (d0 + a_col) * 2);
                ldsm4t(aH[mf], ad);
            }
#pragma unroll
            for (int g = 0; g < 2; g++) {
                int e0 = wn * 32 + g * 16;
                uint32_t bd = sb + KV_TILE +
                              (uint32_t)((kt0 + b_row) * (KV_SR * 2) +
                                         (e0 + b_col) * 2);
                ldsm4t(bH[g], bd);
            }
#pragma unroll
            for (int mf = 0; mf < 2; mf++)
#pragma unroll
                for (int nf = 0; nf < 4; nf++)
                    mma16816h(acc[mf][nf], aH[mf], &bH[nf >> 1][(nf & 1) * 2]);
        }
    }

    float* dbase = g_dots + (size_t)bh * DH * DH;
    const int r0 = lane >> 2, c0 = (lane & 3) * 2;
#pragma unroll
    for (int mf = 0; mf < 2; mf++)
#pragma unroll
        for (int nf = 0; nf < 4; nf++) {
            int d = wm * 32 + mf * 16 + r0;
            int e = wn * 32 + nf * 8 + c0;
            atomicAdd(&dbase[d * DH + e],       acc[mf][nf][0]);
            atomicAdd(&dbase[d * DH + e + 1],   acc[mf][nf][1]);
            atomicAdd(&dbase[(d + 8) * DH + e],     acc[mf][nf][2]);
            atomicAdd(&dbase[(d + 8) * DH + e + 1], acc[mf][nf][3]);
        }
}

__global__ void zero_dots_kernel() {
    g_dots[blockIdx.x * blockDim.x + threadIdx.x] = 0.0f;
}

// ---------------------------------------------------------------------------
// McatT[b][o, h*64+d] = (1/SEQ) * sum_e dots[b,h,d,e] * Wout[o, h*64+e] (fp16)
// ---------------------------------------------------------------------------
__global__ __launch_bounds__(256) void mcat_kernel(const float* __restrict__ Wout) {
    __shared__ float ds[64][65];
    __shared__ float ws[64][65];

    const int bh = blockIdx.x;
    const int b = bh >> 3, h = bh & 7;
    const int o0 = blockIdx.y * 64;
    const int tid = threadIdx.x;

    for (int i = tid; i < 4096; i += 256) {
        int d = i >> 6, e = i & 63;
        ds[d][e] = g_dots[(size_t)bh * 4096 + i];
        ws[d][e] = Wout[(size_t)(o0 + d) * INNER + h * DH + e];
    }
    __syncthreads();

    for (int t = tid; t < 4096; t += 256) {
        int oL = t >> 6, d = t & 63;
        float acc = 0.0f;
#pragma unroll
        for (int e = 0; e < 64; e++) acc += ds[d][e] * ws[oL][e];
        acc *= (1.0f / (float)SEQ);
        size_t idx = ((size_t)b * DIM + (o0 + oL)) * 512 + h * DH + d;
        g_mh[idx] = __float2half(acc);
    }
}

// ---------------------------------------------------------------------------
// launch (single stream, fat launches)
// ---------------------------------------------------------------------------
extern "C" void kernel_launch(void* const* d_in, const int* in_sizes, int n_in,
                              void* d_out, int out_size) {
    const float* x    = (const float*)d_in[0];
    const float* pos  = (const float*)d_in[1];
    const float* Wqkv = (const float*)d_in[2];
    const float* gk   = (const float*)d_in[3];
    const float* bk   = (const float*)d_in[4];
    const float* gv   = (const float*)d_in[5];
    const float* bv   = (const float*)d_in[6];
    const float* Wout = (const float*)d_in[7];
    const float* bout = (const float*)d_in[8];
    float* out = (float*)d_out;

    static bool attr_done = false;
    if (!attr_done) {
        cudaFuncSetAttribute(gemm_qkv_tc,  cudaFuncAttributeMaxDynamicSharedMemorySize, GEMM_SMEM);
        cudaFuncSetAttribute(gemm_out_tc,  cudaFuncAttributeMaxDynamicSharedMemorySize, GEMM_SMEM);
        cudaFuncSetAttribute(kv_dots_kernel, cudaFuncAttributeMaxDynamicSharedMemorySize, KV_SMEM);
        attr_done = true;
    }

    void* p_xh; void* p_wh;
    cudaGetSymbolAddress(&p_xh, g_xh); cudaGetSymbolAddress(&p_wh, g_wh);

    // 1) fp16 converts + dots zero
    int n4x = (ROWS * DIM) / 4;
    split_kernel<<<(n4x + 255) / 256, 256>>>(x, (__half*)p_xh, n4x);
    int n4w = (QKV_COLS * DIM) / 4;
    split_kernel<<<(n4w + 255) / 256, 256>>>(Wqkv, (__half*)p_wh, n4w);
    zero_dots_kernel<<<(BATCH * HEADS * DH * DH) / 256, 256>>>();

    // 2) qkv = x @ Wqkv^T (fp16 HMMA) -> fp16 g_qkvh
    gemm_qkv_tc<<<dim3(QKV_COLS / 128, ROWS / 128), 256, GEMM_SMEM>>>();

    // 3) LN(k,v) + RoPE(q,k) -> fp16 q/k/v
    ln_rope_split_kernel<<<(BATCH * SEQ * HEADS) / 8, 256>>>(pos, gk, bk, gv, bv);

    // 4) dots = K^T V (fp16 HMMA, atomic over 4 splits)
    kv_dots_kernel<<<dim3(BATCH * HEADS, 4), 128, KV_SMEM>>>();

    // 5) McatT[b] = (dots[b] @ Wout^T)/SEQ (fp16)
    mcat_kernel<<<dim3(BATCH * HEADS, DIM / 64), 256>>>(Wout);

    // 6) out[b] = q[b] @ McatT[b]^T + b_out
    gemm_out_tc<<<dim3(DIM / 128, SEQ / 128, BATCH), 256, GEMM_SMEM>>>(bout, out);
}